// round 2
// baseline (speedup 1.0000x reference)
#include <cuda_runtime.h>
#include <math.h>

#define N_PTS  100000
#define PLANES 128
#define VEC    16
#define KOFF   27

// Scratch (allocation-free rule: __device__ globals)
__device__ float g_qf[N_PTS * VEC];       // 6.4 MB
__device__ float g_choice[N_PTS];         // 0.4 MB
__device__ float g_vf[(size_t)N_PTS * PLANES]; // 51.2 MB

// ---------------------------------------------------------------------------
// Kernel 1: sparse 3x3x3 conv  q_pre[n,v] = sum_k m[k,n] * (x[idx[k,n]] . W_q[k,:,v])
//           then q_f = relu(q_pre*gamma + beta)  -> g_qf
// Block = 128 thr (4 warps). Warp handles 16 points (8 pairs of 2).
// W_q[k] staged transposed (stride 132, conflict-free float4 reads) in smem.
// ---------------------------------------------------------------------------
__global__ __launch_bounds__(128) void k_qconv(
    const float* __restrict__ x, const float* __restrict__ W_q,
    const float* __restrict__ q_gamma, const float* __restrict__ q_beta,
    const int* __restrict__ nbr_idx, const int* __restrict__ nbr_mask)
{
    __shared__ float sWqT[VEC * 132];      // transposed W_q[k], padded
    __shared__ float sX[4][2 * PLANES];    // per-warp 2 gathered x rows

    const int tid  = threadIdx.x;
    const int wid  = tid >> 5;
    const int lane = tid & 31;
    const int sub  = lane >> 4;            // which of the 2 points
    const int v    = lane & 15;            // output channel
    const int base = blockIdx.x * 64 + wid * 16;

    // zero-init gather buffers (skipped loads must never read garbage)
    for (int i = tid; i < 4 * 2 * PLANES; i += 128) (&sX[0][0])[i] = 0.f;

    float acc[8];
#pragma unroll
    for (int p = 0; p < 8; p++) acc[p] = 0.f;

    for (int k = 0; k < KOFF; k++) {
        __syncthreads();
        // transpose-load W_q[k]: thread tid owns row j = tid (16 floats)
        {
            const float4* src = (const float4*)(W_q + (size_t)k * PLANES * VEC + tid * VEC);
            float4 a = __ldg(src + 0), b = __ldg(src + 1);
            float4 c = __ldg(src + 2), d = __ldg(src + 3);
            sWqT[ 0*132 + tid] = a.x; sWqT[ 1*132 + tid] = a.y;
            sWqT[ 2*132 + tid] = a.z; sWqT[ 3*132 + tid] = a.w;
            sWqT[ 4*132 + tid] = b.x; sWqT[ 5*132 + tid] = b.y;
            sWqT[ 6*132 + tid] = b.z; sWqT[ 7*132 + tid] = b.w;
            sWqT[ 8*132 + tid] = c.x; sWqT[ 9*132 + tid] = c.y;
            sWqT[10*132 + tid] = c.z; sWqT[11*132 + tid] = c.w;
            sWqT[12*132 + tid] = d.x; sWqT[13*132 + tid] = d.y;
            sWqT[14*132 + tid] = d.z; sWqT[15*132 + tid] = d.w;
        }
        __syncthreads();
        const int kb = k * N_PTS;
#pragma unroll 1
        for (int p = 0; p < 8; p++) {
            const int n0 = base + p * 2;
            const int n1 = n0 + 1;
            int m0 = 0, m1 = 0, i0 = 0, i1 = 0;
            if (n0 < N_PTS) { i0 = __ldg(nbr_idx + kb + n0); m0 = __ldg(nbr_mask + kb + n0); }
            if (n1 < N_PTS) { i1 = __ldg(nbr_idx + kb + n1); m1 = __ldg(nbr_mask + kb + n1); }
            if (m0) ((float4*)&sX[wid][0])[lane]      = __ldg((const float4*)(x + (size_t)i0 * PLANES) + lane);
            if (m1) ((float4*)&sX[wid][PLANES])[lane] = __ldg((const float4*)(x + (size_t)i1 * PLANES) + lane);
            __syncwarp();
            const int m = sub ? m1 : m0;
            if (m) {
                const float4* xr = (const float4*)&sX[wid][sub * PLANES];
                const float4* wr = (const float4*)&sWqT[v * 132];
                float dot = 0.f;
#pragma unroll
                for (int j4 = 0; j4 < PLANES / 4; j4++) {
                    float4 xv = xr[j4];
                    float4 wv = wr[j4];
                    dot = fmaf(xv.x, wv.x, dot);
                    dot = fmaf(xv.y, wv.y, dot);
                    dot = fmaf(xv.z, wv.z, dot);
                    dot = fmaf(xv.w, wv.w, dot);
                }
                acc[p] += dot;
            }
            __syncwarp();
        }
    }

    const float qg = q_gamma[v], qb = q_beta[v];
#pragma unroll
    for (int p = 0; p < 8; p++) {
        const int n = base + p * 2 + sub;
        if (n < N_PTS) {
            float qf = fmaf(acc[p], qg, qb);
            g_qf[n * VEC + v] = qf > 0.f ? qf : 0.f;
        }
    }
}

// ---------------------------------------------------------------------------
// Kernel 2: choice[n] = sum_c relu( sum_j codebook[j]*qf[n,j/8]*W_choice[j,c] + b[c] )
// Block = 128 thr, W_choice in dyn smem, 4 points per iteration (weight reuse).
// ---------------------------------------------------------------------------
__global__ __launch_bounds__(128) void k_choice(
    const float* __restrict__ codebook, const float* __restrict__ W_choice,
    const float* __restrict__ b_choice)
{
    extern __shared__ float sm[];
    float* sW = sm;                      // 128*128
    float* sT = sm + PLANES * PLANES;    // 4*128
    __shared__ float sRed[4][4];         // [warp][point]

    const int tid  = threadIdx.x;
    const int lane = tid & 31, wid = tid >> 5;
    for (int i = tid; i < PLANES * PLANES / 4; i += 128)
        ((float4*)sW)[i] = __ldg((const float4*)W_choice + i);
    const float cb = codebook[tid];
    const float bc = b_choice[tid];
    __syncthreads();

    for (int n0 = blockIdx.x * 4; n0 < N_PTS; n0 += gridDim.x * 4) {
#pragma unroll
        for (int p = 0; p < 4; p++) {
            const int n = n0 + p;
            float q = (n < N_PTS) ? g_qf[n * VEC + (tid >> 3)] : 0.f;
            sT[p * PLANES + tid] = cb * q;
        }
        __syncthreads();
        float y0 = bc, y1 = bc, y2 = bc, y3 = bc;
#pragma unroll 4
        for (int j = 0; j < PLANES; j++) {
            const float w = sW[j * PLANES + tid];
            y0 = fmaf(sT[0 * PLANES + j], w, y0);
            y1 = fmaf(sT[1 * PLANES + j], w, y1);
            y2 = fmaf(sT[2 * PLANES + j], w, y2);
            y3 = fmaf(sT[3 * PLANES + j], w, y3);
        }
        y0 = fmaxf(y0, 0.f); y1 = fmaxf(y1, 0.f);
        y2 = fmaxf(y2, 0.f); y3 = fmaxf(y3, 0.f);
#pragma unroll
        for (int off = 16; off > 0; off >>= 1) {
            y0 += __shfl_xor_sync(0xffffffffu, y0, off);
            y1 += __shfl_xor_sync(0xffffffffu, y1, off);
            y2 += __shfl_xor_sync(0xffffffffu, y2, off);
            y3 += __shfl_xor_sync(0xffffffffu, y3, off);
        }
        if (lane == 0) { sRed[wid][0] = y0; sRed[wid][1] = y1;
                         sRed[wid][2] = y2; sRed[wid][3] = y3; }
        __syncthreads();
        if (tid < 4) {
            const int n = n0 + tid;
            if (n < N_PTS)
                g_choice[n] = sRed[0][tid] + sRed[1][tid] + sRed[2][tid] + sRed[3][tid];
        }
        __syncthreads();
    }
}

// ---------------------------------------------------------------------------
// Kernel 3: v_f = relu((x@W_v)*gamma + beta) + repeat(coords@W_pos + b_pos, 8)
// Block = 128 thr, W_v in dyn smem, 4 points per iteration.
// ---------------------------------------------------------------------------
__global__ __launch_bounds__(128) void k_vf(
    const float* __restrict__ x, const float* __restrict__ coords,
    const float* __restrict__ W_v, const float* __restrict__ v_gamma,
    const float* __restrict__ v_beta, const float* __restrict__ W_pos,
    const float* __restrict__ b_pos)
{
    extern __shared__ float sm[];
    float* sW = sm;                      // 128*128
    float* sX = sm + PLANES * PLANES;    // 4*128
    float* sC = sX + 4 * PLANES;         // 12

    const int tid = threadIdx.x;
    for (int i = tid; i < PLANES * PLANES / 4; i += 128)
        ((float4*)sW)[i] = __ldg((const float4*)W_v + i);
    const float vg = v_gamma[tid], vb = v_beta[tid];
    const int grp = tid >> 3;            // repeated channel group
    const float wp0 = W_pos[0 * VEC + grp];
    const float wp1 = W_pos[1 * VEC + grp];
    const float wp2 = W_pos[2 * VEC + grp];
    const float bp  = b_pos[grp];
    __syncthreads();

    for (int n0 = blockIdx.x * 4; n0 < N_PTS; n0 += gridDim.x * 4) {
        {
            const int r = tid >> 5, c4 = tid & 31;
            const int n = n0 + r;
            float4 val = make_float4(0.f, 0.f, 0.f, 0.f);
            if (n < N_PTS) val = __ldg((const float4*)(x + (size_t)n * PLANES) + c4);
            ((float4*)sX)[tid] = val;
        }
        if (tid < 12) {
            const int n = n0 + tid / 3;
            sC[tid] = (n < N_PTS) ? coords[n * 3 + (tid % 3)] : 0.f;
        }
        __syncthreads();
        float y0 = 0.f, y1 = 0.f, y2 = 0.f, y3 = 0.f;
#pragma unroll 4
        for (int j = 0; j < PLANES; j++) {
            const float w = sW[j * PLANES + tid];
            y0 = fmaf(sX[0 * PLANES + j], w, y0);
            y1 = fmaf(sX[1 * PLANES + j], w, y1);
            y2 = fmaf(sX[2 * PLANES + j], w, y2);
            y3 = fmaf(sX[3 * PLANES + j], w, y3);
        }
        float ys[4] = {y0, y1, y2, y3};
#pragma unroll
        for (int p = 0; p < 4; p++) {
            const int n = n0 + p;
            if (n < N_PTS) {
                float r = fmaf(ys[p], vg, vb);
                r = r > 0.f ? r : 0.f;
                float pos = fmaf(sC[p*3+0], wp0, fmaf(sC[p*3+1], wp1, fmaf(sC[p*3+2], wp2, bp)));
                g_vf[(size_t)n * PLANES + tid] = r + pos;
            }
        }
        __syncthreads();
    }
}

// ---------------------------------------------------------------------------
// Kernel 4: scores s_k = choice[n]*choice[idx]*||codebook||^2 (masked), softmax
//           over K, agg = sum_k w_k * v_f[idx], out = relu((agg@W_out)*g+b) + x
// Block = 128 thr (one output channel each), W_out in dyn smem, 1 point/iter.
// ---------------------------------------------------------------------------
__global__ __launch_bounds__(128) void k_attn_out(
    const float* __restrict__ x, const float* __restrict__ codebook,
    const float* __restrict__ W_out, const float* __restrict__ out_gamma,
    const float* __restrict__ out_beta, const int* __restrict__ nbr_idx,
    const int* __restrict__ nbr_mask, float* __restrict__ out)
{
    extern __shared__ float sm[];
    float* sW   = sm;                     // 128*128
    float* sAgg = sm + PLANES * PLANES;   // 128
    __shared__ float sS[KOFF];
    __shared__ float sE[KOFF];
    __shared__ int   sI[KOFF];

    const int tid = threadIdx.x;
    for (int i = tid; i < PLANES * PLANES / 4; i += 128)
        ((float4*)sW)[i] = __ldg((const float4*)W_out + i);
    const float og = out_gamma[tid], ob = out_beta[tid];
    float csum = 0.f;
    for (int j = 0; j < PLANES; j++) { float c = __ldg(codebook + j); csum = fmaf(c, c, csum); }
    __syncthreads();

    for (int n = blockIdx.x; n < N_PTS; n += gridDim.x) {
        const float chn = g_choice[n];
        if (tid < KOFF) {
            const int idx = __ldg(nbr_idx  + tid * N_PTS + n);
            const int m   = __ldg(nbr_mask + tid * N_PTS + n);
            sI[tid] = idx;
            sS[tid] = m ? chn * g_choice[idx] * csum : -3.0e38f;
        }
        __syncthreads();
        float mx = -3.0e38f;
#pragma unroll
        for (int k = 0; k < KOFF; k++) mx = fmaxf(mx, sS[k]);
        if (tid < KOFF) {
            const float s = sS[tid];
            sE[tid] = (s > -1.0e37f) ? __expf(s - mx) : 0.f;
        }
        __syncthreads();
        float den = 0.f;
#pragma unroll
        for (int k = 0; k < KOFF; k++) den += sE[k];
        const float rden = 1.0f / den;

        float acc = 0.f;
#pragma unroll 1
        for (int k = 0; k < KOFF; k++) {
            const float e = sE[k];               // uniform across block
            if (e != 0.f)
                acc = fmaf(e, __ldg(g_vf + (size_t)sI[k] * PLANES + tid), acc);
        }
        sAgg[tid] = acc * rden;
        __syncthreads();

        float y = 0.f;
#pragma unroll 4
        for (int j = 0; j < PLANES; j++)
            y = fmaf(sAgg[j], sW[j * PLANES + tid], y);
        float r = fmaf(y, og, ob);
        r = r > 0.f ? r : 0.f;
        out[(size_t)n * PLANES + tid] = r + x[(size_t)n * PLANES + tid];
        __syncthreads();
    }
}

// ---------------------------------------------------------------------------
extern "C" void kernel_launch(void* const* d_in, const int* in_sizes, int n_in,
                              void* d_out, int out_size)
{
    const float* x         = (const float*)d_in[0];
    const float* coords    = (const float*)d_in[1];
    const float* W_q       = (const float*)d_in[2];
    const float* q_gamma   = (const float*)d_in[3];
    const float* q_beta    = (const float*)d_in[4];
    const float* W_v       = (const float*)d_in[5];
    const float* v_gamma   = (const float*)d_in[6];
    const float* v_beta    = (const float*)d_in[7];
    const float* codebook  = (const float*)d_in[8];
    const float* W_choice  = (const float*)d_in[9];
    const float* b_choice  = (const float*)d_in[10];
    const float* W_pos     = (const float*)d_in[11];
    const float* b_pos     = (const float*)d_in[12];
    const float* W_out     = (const float*)d_in[13];
    const float* out_gamma = (const float*)d_in[14];
    const float* out_beta  = (const float*)d_in[15];
    const int*   nbr_idx   = (const int*)d_in[16];
    const int*   nbr_mask  = (const int*)d_in[17];
    float* out = (float*)d_out;

    const int smem_choice = (PLANES * PLANES + 4 * PLANES) * (int)sizeof(float);
    const int smem_vf     = (PLANES * PLANES + 4 * PLANES + 16) * (int)sizeof(float);
    const int smem_attn   = (PLANES * PLANES + PLANES) * (int)sizeof(float);
    cudaFuncSetAttribute(k_choice,   cudaFuncAttributeMaxDynamicSharedMemorySize, smem_choice);
    cudaFuncSetAttribute(k_vf,       cudaFuncAttributeMaxDynamicSharedMemorySize, smem_vf);
    cudaFuncSetAttribute(k_attn_out, cudaFuncAttributeMaxDynamicSharedMemorySize, smem_attn);

    k_qconv<<<(N_PTS + 63) / 64, 128>>>(x, W_q, q_gamma, q_beta, nbr_idx, nbr_mask);
    k_vf<<<1184, 128, smem_vf>>>(x, coords, W_v, v_gamma, v_beta, W_pos, b_pos);
    k_choice<<<1184, 128, smem_choice>>>(codebook, W_choice, b_choice);
    k_attn_out<<<2960, 128, smem_attn>>>(x, codebook, W_out, out_gamma, out_beta,
                                         nbr_idx, nbr_mask, out);
}

// round 6
// speedup vs baseline: 3.2628x; 3.2628x over previous
#include <cuda_runtime.h>
#include <math.h>

#define N_PTS  100000
#define PLANES 128
#define VEC    16
#define KOFF   27
#define NCH    432        // KOFF * VEC
#define N_TILES 3125      // N_PTS / 32 (exact)

// Scratch (__device__ globals: allocation-free rule)
__device__ float g_y[(size_t)N_PTS * NCH];        // 172.8 MB
__device__ float g_choice[N_PTS];                 // 0.4 MB
__device__ float g_vf[(size_t)N_PTS * PLANES];    // 51.2 MB
__device__ float g_A[VEC * PLANES];               // folded codebook*W_choice
__device__ float g_csum;                          // ||codebook||^2

// ---------------------------------------------------------------------------
// Kernel 0: A[v][c] = sum_{j in 8v..8v+7} codebook[j] * W_choice[j][c];  csum
// ---------------------------------------------------------------------------
__global__ void k_prep(const float* __restrict__ codebook,
                       const float* __restrict__ W_choice)
{
    const int c = threadIdx.x;   // 128 threads
    for (int v = 0; v < VEC; v++) {
        float s = 0.f;
#pragma unroll
        for (int j = 0; j < 8; j++) {
            const int jj = v * 8 + j;
            s = fmaf(__ldg(codebook + jj), __ldg(W_choice + jj * PLANES + c), s);
        }
        g_A[v * PLANES + c] = s;
    }
    if (c == 0) {
        float cs = 0.f;
        for (int j = 0; j < PLANES; j++) { float t = __ldg(codebook + j); cs = fmaf(t, t, cs); }
        g_csum = cs;
    }
}

// ---------------------------------------------------------------------------
// Kernel 1: dense GEMM  y[n, k*16+v] = sum_j x[n,j] * W_q[k,j,v]
// Block = 128 thr, tile 128 points. x tile staged once, W_q[k] restaged per k.
// Thread tile: 4 points (pg=tid>>2) x 4 v (vg=tid&3). Conflict-free smem.
// ---------------------------------------------------------------------------
__global__ __launch_bounds__(128) void k_ygemm(
    const float* __restrict__ x, const float* __restrict__ W_q)
{
    extern __shared__ float sm[];
    float* sX = sm;                  // 128 * 132
    float* sW = sm + PLANES * 132;   // 16 * 132 (row perm: ridx(v)=(v&3)*4+(v>>2))

    const int tid = threadIdx.x;
    const int n0  = blockIdx.x * PLANES;

    // stage x tile (coalesced float4), zero-fill tail
    for (int r = 0; r < 32; r++) {
        const int id = r * 128 + tid;
        const int p = id >> 5, c4 = id & 31;
        const int n = n0 + p;
        float4 v = make_float4(0.f, 0.f, 0.f, 0.f);
        if (n < N_PTS) v = __ldg((const float4*)(x + (size_t)n * PLANES) + c4);
        *(float4*)&sX[p * 132 + c4 * 4] = v;
    }

    const int pg = tid >> 2, vg = tid & 3;
    const float* xb = &sX[(pg * 4) * 132];
    const float* wb = &sW[vg * 132];

    for (int k = 0; k < KOFF; k++) {
        __syncthreads();
        {   // stage W_q[k]: thread = row j, transpose+permute (v -> row (v&3)*4+(v>>2))
            const float4* src = (const float4*)(W_q + (size_t)k * PLANES * VEC + tid * VEC);
            float4 a = __ldg(src + 0), b = __ldg(src + 1);
            float4 c = __ldg(src + 2), d = __ldg(src + 3);
            sW[ 0*132 + tid] = a.x; sW[ 4*132 + tid] = a.y; sW[ 8*132 + tid] = a.z; sW[12*132 + tid] = a.w;
            sW[ 1*132 + tid] = b.x; sW[ 5*132 + tid] = b.y; sW[ 9*132 + tid] = b.z; sW[13*132 + tid] = b.w;
            sW[ 2*132 + tid] = c.x; sW[ 6*132 + tid] = c.y; sW[10*132 + tid] = c.z; sW[14*132 + tid] = c.w;
            sW[ 3*132 + tid] = d.x; sW[ 7*132 + tid] = d.y; sW[11*132 + tid] = d.z; sW[15*132 + tid] = d.w;
        }
        __syncthreads();

        float acc[4][4];
#pragma unroll
        for (int i = 0; i < 4; i++)
#pragma unroll
            for (int i2 = 0; i2 < 4; i2++) acc[i][i2] = 0.f;

#pragma unroll 4
        for (int jj = 0; jj < 32; jj++) {
            float4 xv[4];
#pragma unroll
            for (int i = 0; i < 4; i++) xv[i] = *(const float4*)&xb[i * 132 + jj * 4];
#pragma unroll
            for (int i2 = 0; i2 < 4; i2++) {
                const float4 wv = *(const float4*)&wb[i2 * 4 * 132 + jj * 4];
#pragma unroll
                for (int i = 0; i < 4; i++) {
                    acc[i][i2] = fmaf(xv[i].x, wv.x, acc[i][i2]);
                    acc[i][i2] = fmaf(xv[i].y, wv.y, acc[i][i2]);
                    acc[i][i2] = fmaf(xv[i].z, wv.z, acc[i][i2]);
                    acc[i][i2] = fmaf(xv[i].w, wv.w, acc[i][i2]);
                }
            }
        }
#pragma unroll
        for (int i = 0; i < 4; i++) {
            const int n = n0 + pg * 4 + i;
            if (n < N_PTS)
                *(float4*)&g_y[(size_t)n * NCH + k * VEC + vg * 4] =
                    make_float4(acc[i][0], acc[i][1], acc[i][2], acc[i][3]);
        }
    }
}

// ---------------------------------------------------------------------------
// Kernel 2: warp-per-point. q_pre[v] = sum_k m * y[idx,k,v]; qf = relu(bn);
//           choice = sum_c relu(qf . A[:,c] + b_c)   -> g_choice
// ---------------------------------------------------------------------------
__global__ __launch_bounds__(256) void k_qchoice(
    const float* __restrict__ q_gamma, const float* __restrict__ q_beta,
    const float* __restrict__ b_choice,
    const int* __restrict__ nbr_idx, const int* __restrict__ nbr_mask)
{
    __shared__ float sA[VEC * PLANES];
    const int tid = threadIdx.x, lane = tid & 31, w = tid >> 5;
    for (int i = tid; i < VEC * PLANES / 4; i += 256)
        ((float4*)sA)[i] = __ldg((const float4*)g_A + i);
    __syncthreads();

    const int n = blockIdx.x * 8 + w;   // grid = 12500 -> exactly N_PTS warps

    int idxv = 0, mk = 0;
    if (lane < KOFF) {
        idxv = __ldg(nbr_idx  + lane * N_PTS + n);
        mk   = __ldg(nbr_mask + lane * N_PTS + n);
    }
    float acc = 0.f;
#pragma unroll
    for (int k = 0; k < KOFF; k++) {
        const int id = __shfl_sync(0xffffffffu, idxv, k);
        const int m  = __shfl_sync(0xffffffffu, mk,   k);
        float t = 0.f;
        if (m && lane < VEC) t = __ldg(g_y + (size_t)id * NCH + k * VEC + lane);
        acc += t;
    }
    float qf = 0.f;
    if (lane < VEC) {
        qf = fmaf(acc, __ldg(q_gamma + lane), __ldg(q_beta + lane));
        qf = fmaxf(qf, 0.f);
    }
    float s0 = __ldg(b_choice + lane);
    float s1 = __ldg(b_choice + 32 + lane);
    float s2 = __ldg(b_choice + 64 + lane);
    float s3 = __ldg(b_choice + 96 + lane);
#pragma unroll
    for (int v = 0; v < VEC; v++) {
        const float qv = __shfl_sync(0xffffffffu, qf, v);
        s0 = fmaf(qv, sA[v * PLANES +      lane], s0);
        s1 = fmaf(qv, sA[v * PLANES + 32 + lane], s1);
        s2 = fmaf(qv, sA[v * PLANES + 64 + lane], s2);
        s3 = fmaf(qv, sA[v * PLANES + 96 + lane], s3);
    }
    float tsum = fmaxf(s0, 0.f) + fmaxf(s1, 0.f) + fmaxf(s2, 0.f) + fmaxf(s3, 0.f);
#pragma unroll
    for (int off = 16; off > 0; off >>= 1)
        tsum += __shfl_xor_sync(0xffffffffu, tsum, off);
    if (lane == 0) g_choice[n] = tsum;
}

// ---------------------------------------------------------------------------
// Kernel 3: v_f = relu((x@W_v)*gamma+beta) + repeat(coords@W_pos + b_pos, 8)
// Persistent blocks, tile = 32 points, thread tile 4p x 8c, W_v staged once.
// Row permutation perm(c) = (c&7)*16 + (c>>3) -> conflict-free channel reads.
// ---------------------------------------------------------------------------
__global__ __launch_bounds__(128) void k_vf(
    const float* __restrict__ x, const float* __restrict__ coords,
    const float* __restrict__ W_v, const float* __restrict__ v_gamma,
    const float* __restrict__ v_beta, const float* __restrict__ W_pos,
    const float* __restrict__ b_pos)
{
    extern __shared__ float sm[];
    float* sW = sm;                  // 128 * 132
    float* sX = sm + PLANES * 132;   // 32 * 132
    float* sC = sX + 32 * 132;       // 32 * 4

    const int tid = threadIdx.x;
    const int pg = tid >> 4, cg = tid & 15;

    for (int r = 0; r < 32; r++) {
        const int id = r * 128 + tid;
        const int j = id >> 5, c0 = (id & 31) * 4;
        const float4 v = __ldg((const float4*)W_v + id);
        sW[(((c0+0)&7)*16 + ((c0+0)>>3))*132 + j] = v.x;
        sW[(((c0+1)&7)*16 + ((c0+1)>>3))*132 + j] = v.y;
        sW[(((c0+2)&7)*16 + ((c0+2)>>3))*132 + j] = v.z;
        sW[(((c0+3)&7)*16 + ((c0+3)>>3))*132 + j] = v.w;
    }
    float gam[8], bet[8];
#pragma unroll
    for (int t = 0; t < 8; t++) {
        const int c = cg * 8 + t;
        gam[t] = __ldg(v_gamma + c); bet[t] = __ldg(v_beta + c);
    }
    const float wp0 = __ldg(W_pos + 0 * VEC + cg);
    const float wp1 = __ldg(W_pos + 1 * VEC + cg);
    const float wp2 = __ldg(W_pos + 2 * VEC + cg);
    const float bp  = __ldg(b_pos + cg);

    for (int tile = blockIdx.x; tile < N_TILES; tile += gridDim.x) {
        __syncthreads();
        for (int r = 0; r < 8; r++) {
            const int id = r * 128 + tid;
            const int p = id >> 5, c4 = id & 31;
            const int n = tile * 32 + p;
            *(float4*)&sX[p * 132 + c4 * 4] =
                __ldg((const float4*)(x + (size_t)n * PLANES) + c4);
        }
        if (tid < 32) {
            const int n = tile * 32 + tid;
            sC[tid*4+0] = __ldg(coords + n*3 + 0);
            sC[tid*4+1] = __ldg(coords + n*3 + 1);
            sC[tid*4+2] = __ldg(coords + n*3 + 2);
        }
        __syncthreads();

        float acc[4][8];
#pragma unroll
        for (int i = 0; i < 4; i++)
#pragma unroll
            for (int t = 0; t < 8; t++) acc[i][t] = 0.f;

        const float* xb = &sX[(pg * 4) * 132];
        const float* wb = &sW[cg * 132];
#pragma unroll 2
        for (int jj = 0; jj < 32; jj++) {
            float4 xv[4];
#pragma unroll
            for (int i = 0; i < 4; i++) xv[i] = *(const float4*)&xb[i * 132 + jj * 4];
#pragma unroll
            for (int t = 0; t < 8; t++) {
                const float4 wv = *(const float4*)&wb[t * 16 * 132 + jj * 4];
#pragma unroll
                for (int i = 0; i < 4; i++) {
                    acc[i][t] = fmaf(xv[i].x, wv.x, acc[i][t]);
                    acc[i][t] = fmaf(xv[i].y, wv.y, acc[i][t]);
                    acc[i][t] = fmaf(xv[i].z, wv.z, acc[i][t]);
                    acc[i][t] = fmaf(xv[i].w, wv.w, acc[i][t]);
                }
            }
        }
#pragma unroll
        for (int i = 0; i < 4; i++) {
            const int p = pg * 4 + i;
            const int n = tile * 32 + p;
            const float pos = fmaf(sC[p*4+0], wp0,
                              fmaf(sC[p*4+1], wp1,
                              fmaf(sC[p*4+2], wp2, bp)));
            float o[8];
#pragma unroll
            for (int t = 0; t < 8; t++) {
                const float r = fmaf(acc[i][t], gam[t], bet[t]);
                o[t] = fmaxf(r, 0.f) + pos;
            }
            float4* dst = (float4*)(g_vf + (size_t)n * PLANES + cg * 8);
            dst[0] = make_float4(o[0], o[1], o[2], o[3]);
            dst[1] = make_float4(o[4], o[5], o[6], o[7]);
        }
    }
}

// ---------------------------------------------------------------------------
// Kernel 4: warp-per-point softmax + v_f gather-aggregate into smem, then
//           tile GEMM out = relu((agg@W_out)*gamma+beta) + x.
// ---------------------------------------------------------------------------
__global__ __launch_bounds__(128) void k_attn_out(
    const float* __restrict__ x, const float* __restrict__ W_out,
    const float* __restrict__ out_gamma, const float* __restrict__ out_beta,
    const int* __restrict__ nbr_idx, const int* __restrict__ nbr_mask,
    float* __restrict__ out)
{
    extern __shared__ float sm[];
    float* sW   = sm;                 // 128 * 132
    float* sAgg = sm + PLANES * 132;  // 32 * 132

    const int tid = threadIdx.x;
    const int lane = tid & 31, w = tid >> 5;
    const int pg = tid >> 4, cg = tid & 15;

    for (int r = 0; r < 32; r++) {
        const int id = r * 128 + tid;
        const int j = id >> 5, c0 = (id & 31) * 4;
        const float4 v = __ldg((const float4*)W_out + id);
        sW[(((c0+0)&7)*16 + ((c0+0)>>3))*132 + j] = v.x;
        sW[(((c0+1)&7)*16 + ((c0+1)>>3))*132 + j] = v.y;
        sW[(((c0+2)&7)*16 + ((c0+2)>>3))*132 + j] = v.z;
        sW[(((c0+3)&7)*16 + ((c0+3)>>3))*132 + j] = v.w;
    }
    float gam[8], bet[8];
#pragma unroll
    for (int t = 0; t < 8; t++) {
        const int c = cg * 8 + t;
        gam[t] = __ldg(out_gamma + c); bet[t] = __ldg(out_beta + c);
    }
    const float csum = g_csum;

    for (int tile = blockIdx.x; tile < N_TILES; tile += gridDim.x) {
        __syncthreads();
        // ---- phase A: each warp aggregates 8 points
#pragma unroll 1
        for (int pp = 0; pp < 8; pp++) {
            const int pl = w * 8 + pp;
            const int n  = tile * 32 + pl;
            const float chn = __ldg(g_choice + n);
            int idxv = 0, mk = 0;
            if (lane < KOFF) {
                idxv = __ldg(nbr_idx  + lane * N_PTS + n);
                mk   = __ldg(nbr_mask + lane * N_PTS + n);
            }
            float s = (mk != 0) ? chn * __ldg(g_choice + idxv) * csum : -3.0e38f;
            float mx = s;
#pragma unroll
            for (int off = 16; off > 0; off >>= 1)
                mx = fmaxf(mx, __shfl_xor_sync(0xffffffffu, mx, off));
            const float e = (mk != 0) ? __expf(s - mx) : 0.f;
            float den = e;
#pragma unroll
            for (int off = 16; off > 0; off >>= 1)
                den += __shfl_xor_sync(0xffffffffu, den, off);
            const float rd = 1.0f / den;

            float ax = 0.f, ay = 0.f, az = 0.f, aw2 = 0.f;
#pragma unroll
            for (int k0 = 0; k0 < KOFF; k0 += 9) {
                float wk[9]; int ik[9];
#pragma unroll
                for (int q = 0; q < 9; q++) {
                    wk[q] = __shfl_sync(0xffffffffu, e,    k0 + q);
                    ik[q] = __shfl_sync(0xffffffffu, idxv, k0 + q);
                }
                float4 t[9];
#pragma unroll
                for (int q = 0; q < 9; q++) {
                    t[q] = make_float4(0.f, 0.f, 0.f, 0.f);
                    if (wk[q] != 0.f)
                        t[q] = __ldg((const float4*)(g_vf + (size_t)ik[q] * PLANES) + lane);
                }
#pragma unroll
                for (int q = 0; q < 9; q++) {
                    ax  = fmaf(wk[q], t[q].x, ax);
                    ay  = fmaf(wk[q], t[q].y, ay);
                    az  = fmaf(wk[q], t[q].z, az);
                    aw2 = fmaf(wk[q], t[q].w, aw2);
                }
            }
            *(float4*)&sAgg[pl * 132 + lane * 4] =
                make_float4(ax * rd, ay * rd, az * rd, aw2 * rd);
        }
        __syncthreads();

        // ---- phase B: 32x128 @ 128x128 tile GEMM + epilogue
        float acc[4][8];
#pragma unroll
        for (int i = 0; i < 4; i++)
#pragma unroll
            for (int t = 0; t < 8; t++) acc[i][t] = 0.f;

        const float* xb = &sAgg[(pg * 4) * 132];
        const float* wb = &sW[cg * 132];
#pragma unroll 2
        for (int jj = 0; jj < 32; jj++) {
            float4 xv[4];
#pragma unroll
            for (int i = 0; i < 4; i++) xv[i] = *(const float4*)&xb[i * 132 + jj * 4];
#pragma unroll
            for (int t = 0; t < 8; t++) {
                const float4 wv = *(const float4*)&wb[t * 16 * 132 + jj * 4];
#pragma unroll
                for (int i = 0; i < 4; i++) {
                    acc[i][t] = fmaf(xv[i].x, wv.x, acc[i][t]);
                    acc[i][t] = fmaf(xv[i].y, wv.y, acc[i][t]);
                    acc[i][t] = fmaf(xv[i].z, wv.z, acc[i][t]);
                    acc[i][t] = fmaf(xv[i].w, wv.w, acc[i][t]);
                }
            }
        }
#pragma unroll
        for (int i = 0; i < 4; i++) {
            const int n = tile * 32 + pg * 4 + i;
            const float4* xr = (const float4*)(x + (size_t)n * PLANES + cg * 8);
            const float4 x0 = __ldg(xr), x1 = __ldg(xr + 1);
            float o[8];
#pragma unroll
            for (int t = 0; t < 8; t++) {
                const float r = fmaf(acc[i][t], gam[t], bet[t]);
                o[t] = fmaxf(r, 0.f);
            }
            float4* dst = (float4*)(out + (size_t)n * PLANES + cg * 8);
            dst[0] = make_float4(o[0] + x0.x, o[1] + x0.y, o[2] + x0.z, o[3] + x0.w);
            dst[1] = make_float4(o[4] + x1.x, o[5] + x1.y, o[6] + x1.z, o[7] + x1.w);
        }
    }
}

// ---------------------------------------------------------------------------
extern "C" void kernel_launch(void* const* d_in, const int* in_sizes, int n_in,
                              void* d_out, int out_size)
{
    const float* x         = (const float*)d_in[0];
    const float* coords    = (const float*)d_in[1];
    const float* W_q       = (const float*)d_in[2];
    const float* q_gamma   = (const float*)d_in[3];
    const float* q_beta    = (const float*)d_in[4];
    const float* W_v       = (const float*)d_in[5];
    const float* v_gamma   = (const float*)d_in[6];
    const float* v_beta    = (const float*)d_in[7];
    const float* codebook  = (const float*)d_in[8];
    const float* W_choice  = (const float*)d_in[9];
    const float* b_choice  = (const float*)d_in[10];
    const float* W_pos     = (const float*)d_in[11];
    const float* b_pos     = (const float*)d_in[12];
    const float* W_out     = (const float*)d_in[13];
    const float* out_gamma = (const float*)d_in[14];
    const float* out_beta  = (const float*)d_in[15];
    const int*   nbr_idx   = (const int*)d_in[16];
    const int*   nbr_mask  = (const int*)d_in[17];
    float* out = (float*)d_out;

    const int smem_y    = (PLANES * 132 + VEC * 132) * (int)sizeof(float);           // 76032
    const int smem_vf   = (PLANES * 132 + 32 * 132 + 128) * (int)sizeof(float);      // 84992
    const int smem_attn = (PLANES * 132 + 32 * 132) * (int)sizeof(float);            // 84480
    cudaFuncSetAttribute(k_ygemm,    cudaFuncAttributeMaxDynamicSharedMemorySize, smem_y);
    cudaFuncSetAttribute(k_vf,       cudaFuncAttributeMaxDynamicSharedMemorySize, smem_vf);
    cudaFuncSetAttribute(k_attn_out, cudaFuncAttributeMaxDynamicSharedMemorySize, smem_attn);

    k_prep<<<1, 128>>>(codebook, W_choice);
    k_ygemm<<<(N_PTS + 127) / 128, 128, smem_y>>>(x, W_q);
    k_vf<<<296, 128, smem_vf>>>(x, coords, W_v, v_gamma, v_beta, W_pos, b_pos);
    k_qchoice<<<N_PTS / 8, 256>>>(q_gamma, q_beta, b_choice, nbr_idx, nbr_mask);
    k_attn_out<<<296, 128, smem_attn>>>(x, W_out, out_gamma, out_beta,
                                        nbr_idx, nbr_mask, out);
}